// round 1
// baseline (speedup 1.0000x reference)
#include <cuda_runtime.h>

// B-spline layer: out[b,f] = sum_k basis(x[b,f])_k * C[k,f] + bias[f]
// degree-3 B-spline, 68 extended knots, 64 basis functions, local support of 4.
//
// Knot vector (float32 of the numpy/double values):
//   idx 0..2 : -0.0035, -0.0030, -0.0025        (left extension)
//   idx 3..5 : -0.002 + 0.0005*(idx-3)          (-0.002, -0.0015, -0.001)
//   idx 6..61: (idx-6)/55                       (uniform interior, t[6]=0, t[61]=1)
//   idx 62..64: 1.001 + 0.0005*(idx-62)
//   idx 65..67: 1.0025, 1.0030, 1.0035          (right extension)
// x in [0,1) => interval j = 6 + floor(x*55), needs knots idx in [4,63] only.

#define NBATCH 4096
#define NF 256
#define NK 64
#define FEAT_TILE 32
#define ROWS_PER_BLOCK 32

__device__ __forceinline__ float knot_f(int idx) {
    // valid for idx in [4, 63]
    float v = (float)(idx - 6) * (1.0f / 55.0f);
    if (idx < 6)  v = -0.002f + 0.0005f * (float)(idx - 3);
    if (idx > 61) v = 1.001f + 0.0005f * (float)(idx - 62);
    return v;
}

__global__ __launch_bounds__(256) void BSL_25898652795515_kernel(
    const float* __restrict__ X,      // (4096, 256)
    const float* __restrict__ C,      // (64, 256)
    const float* __restrict__ bias,   // (256,)
    float* __restrict__ out)          // (4096, 256)
{
    __shared__ float sC[NK * FEAT_TILE];   // 8 KB control-point tile

    const int f0   = blockIdx.y * FEAT_TILE;
    const int row0 = blockIdx.x * ROWS_PER_BLOCK;
    const int tid  = threadIdx.x;

    // Cooperative load of control tile: sC[k*32 + c] = C[k*256 + f0 + c]
    #pragma unroll
    for (int idx = tid; idx < NK * FEAT_TILE; idx += 256) {
        int k = idx >> 5;
        int c = idx & 31;
        sC[idx] = C[k * NF + f0 + c];
    }
    __syncthreads();

    const int lane = tid & 31;
    const int wrp  = tid >> 5;
    const int f    = f0 + lane;
    const float bf = bias[f];

    // Reciprocal denominators (only 6 distinct values across all intervals)
    const float inv1 = 55.0f;                                    // 1/(1/55)
    const float r2c  = 27.5f;                                    // 1/(2/55)
    const float r3c  = (float)(55.0 / 3.0);                      // 1/(3/55)
    const float rA   = (float)(1.0 / (1.0 / 55.0 + 0.001));
    const float rB   = (float)(1.0 / (2.0 / 55.0 + 0.001));
    const float rC   = (float)(1.0 / (1.0 / 55.0 + 0.0015));

    #pragma unroll
    for (int it = 0; it < ROWS_PER_BLOCK / 8; ++it) {
        const int b = row0 + wrp + it * 8;
        const float x = X[b * NF + f];

        int ii = (int)(x * 55.0f);
        ii = max(0, min(54, ii));
        const int j = ii + 6;

        const float tm2 = knot_f(j - 2), tm1 = knot_f(j - 1), t0 = knot_f(j);
        const float t1  = knot_f(j + 1), t2  = knot_f(j + 2), t3 = knot_f(j + 3);

        const float l1 = x - t0, l2 = x - tm1, l3 = x - tm2;
        const float r1 = t1 - x, r2 = t2 - x, r3 = t3 - x;

        // interval-dependent reciprocal denominators (branchless selects)
        const float inv21 = (ii == 0)  ? rA : r2c;                       // t[j+1]-t[j-1]
        const float inv22 = (ii == 54) ? rA : r2c;                       // t[j+2]-t[j]
        const float inv31 = (ii == 0)  ? rC : ((ii == 1)  ? rB : r3c);   // t[j+1]-t[j-2]
        const float inv32 = (ii == 0 || ii == 54) ? rB : r3c;            // t[j+2]-t[j-1]
        const float inv33 = (ii == 54) ? rC : ((ii == 53) ? rB : r3c);   // t[j+3]-t[j]

        // de Boor (degree 3), unrolled; N[r] = B_{ii+3+r}(x)
        // k = 1
        float N0 = r1 * inv1;
        float N1 = l1 * inv1;
        // k = 2
        float temp  = N0 * inv21;
        N0          = r1 * temp;
        float saved = l2 * temp;
        temp        = N1 * inv22;
        N1          = saved + r2 * temp;
        float N2    = l1 * temp;
        // k = 3
        temp  = N0 * inv31;
        N0    = r1 * temp;
        saved = l3 * temp;
        temp  = N1 * inv32;
        N1    = saved + r2 * temp;
        saved = l2 * temp;
        temp  = N2 * inv33;
        N2    = saved + r3 * temp;
        const float N3 = l1 * temp;

        // dot with 4 control rows (bank-conflict-free: bank == lane)
        const int base = (ii + 3) * FEAT_TILE + lane;
        float acc = bf;
        acc += N0 * sC[base];
        acc += N1 * sC[base + 32];
        acc += N2 * sC[base + 64];
        acc += N3 * sC[base + 96];

        out[b * NF + f] = acc;
    }
}

extern "C" void kernel_launch(void* const* d_in, const int* in_sizes, int n_in,
                              void* d_out, int out_size) {
    const float* x    = (const float*)d_in[0];   // (4096, 256)
    const float* ctrl = (const float*)d_in[1];   // (64, 256)
    const float* bias = (const float*)d_in[2];   // (256,)
    float* out = (float*)d_out;

    dim3 grid(NBATCH / ROWS_PER_BLOCK, NF / FEAT_TILE);  // (128, 8)
    BSL_25898652795515_kernel<<<grid, 256>>>(x, ctrl, bias, out);
}